// round 1
// baseline (speedup 1.0000x reference)
#include <cuda_runtime.h>
#include <cstdint>

#define THREADS 256
#define CAP 2048          // candidate buffer capacity (supports k <= CAP)

// Monotone float<->uint key mapping (total order matching IEEE float order)
__device__ __forceinline__ unsigned f2key(float f) {
    unsigned u = __float_as_uint(f);
    return (u & 0x80000000u) ? ~u : (u | 0x80000000u);
}
__device__ __forceinline__ float key2f(unsigned kk) {
    unsigned u = (kk & 0x80000000u) ? (kk ^ 0x80000000u) : ~kk;
    return __uint_as_float(u);
}

// Warp-aggregated append of f into s_cand (counter counts ALL hits, stores clamp at CAP)
__device__ __forceinline__ void warp_append(bool pred, float f, float* s_cand, int* s_cnt, int lane) {
    unsigned mask = __ballot_sync(0xFFFFFFFFu, pred);
    if (pred) {
        int leader = __ffs(mask) - 1;
        int pos_in = __popc(mask & ((1u << lane) - 1u));
        int base = 0;
        if (lane == leader) base = atomicAdd(s_cnt, __popc(mask));
        base = __shfl_sync(mask, base, leader);
        int slot = base + pos_in;
        if (slot < CAP) s_cand[slot] = f;
    }
}

// Exact ranking of M candidates; writes ranks < k. Tie-break by slot index (stable,
// identical values -> identical output regardless of append order => deterministic).
__device__ __forceinline__ void rank_and_write(const float* s_cand, int M, int k,
                                               float* outr, int tid) {
    for (int i = tid; i < M; i += THREADS) {
        float vi = s_cand[i];
        int rank = 0;
        for (int j = 0; j < M; j++) {
            float vj = s_cand[j];
            rank += (vj > vi) || (vj == vi && j < i);
        }
        if (rank < k) outr[rank] = vi;
    }
}

__global__ void TopKPooling_20796231647786_kernel(
    const float* __restrict__ x, const int* __restrict__ kp,
    float* __restrict__ out, long long n_x, long long out_n)
{
    __shared__ float s_cand[CAP];
    __shared__ int s_cnt;
    __shared__ int s_c2;

    const int k = *kp;                       // k lives on device; works for int32 or LE int64
    const long long rows = out_n / k;
    const int row_len = (int)(n_x / rows);
    const int tid = threadIdx.x;
    const int lane = tid & 31;
    const float t0 = 2.35f;                  // fast-path pre-filter; fallback keeps it exact

    for (long long r = blockIdx.x; r < rows; r += gridDim.x) {
        const float* __restrict__ xr = x + r * (long long)row_len;
        float* __restrict__ outr = out + r * (long long)k;

        if (tid == 0) s_cnt = 0;
        __syncthreads();

        // ---- Fast path: single streaming pass, filter x > t0 ----
        const int nv4 = row_len >> 2;
        const float4* __restrict__ x4 = (const float4*)xr;
        for (int i = tid; i < nv4; i += THREADS) {
            float4 v = __ldg(&x4[i]);
            #pragma unroll
            for (int e = 0; e < 4; e++) {
                float f = (e == 0) ? v.x : (e == 1) ? v.y : (e == 2) ? v.z : v.w;
                warp_append(f > t0, f, s_cand, &s_cnt, lane);
            }
        }
        // scalar tail (uniform trip count so ballots stay converged)
        for (int i0 = nv4 << 2; i0 < row_len; i0 += THREADS) {
            int i = i0 + tid;
            bool in = i < row_len;
            float f = in ? __ldg(&xr[i]) : 0.0f;
            warp_append(in && (f > t0), f, s_cand, &s_cnt, lane);
        }
        __syncthreads();

        int c = s_cnt;
        if (c >= k && c <= CAP) {
            // all top-k are strictly > t0 and captured: exact rank among c candidates
            rank_and_write(s_cand, c, k, outr, tid);
        } else {
            // ---- Exact fallback: bisection for the k-th largest key (never taken on
            // the benchmark distribution; guarantees correctness for any input, k<=CAP)
            long long lo = -1, hi = 0xFFFFFFFFll;    // c(lo) >= k > c(hi) invariant target
            while (lo + 1 < hi) {
                long long mid = (lo + hi) >> 1;
                unsigned tkey = (unsigned)mid;
                if (tid == 0) s_c2 = 0;
                __syncthreads();
                int local = 0;
                for (int i = tid; i < row_len; i += THREADS)
                    local += (f2key(__ldg(&xr[i])) > tkey) ? 1 : 0;
                #pragma unroll
                for (int o = 16; o; o >>= 1) local += __shfl_down_sync(0xFFFFFFFFu, local, o);
                if (lane == 0) atomicAdd(&s_c2, local);
                __syncthreads();
                int cc = s_c2;
                if (cc < k) hi = mid; else lo = mid;
                __syncthreads();
            }
            unsigned K = (unsigned)hi;               // K = k-th largest key
            if (tid == 0) s_cnt = 0;
            __syncthreads();
            for (int i0 = 0; i0 < row_len; i0 += THREADS) {
                int i = i0 + tid;
                bool in = i < row_len;
                float f = in ? __ldg(&xr[i]) : 0.0f;
                warp_append(in && (f2key(f) > K), f, s_cand, &s_cnt, lane);
            }
            __syncthreads();
            int M = s_cnt;                            // M < k <= CAP
            rank_and_write(s_cand, M, k, outr, tid);
            float fk = key2f(K);                      // fill duplicates of the k-th value
            for (int i = M + tid; i < k; i += THREADS) outr[i] = fk;
        }
        __syncthreads();   // protect s_cnt/s_cand reuse across row iterations
    }
}

extern "C" void kernel_launch(void* const* d_in, const int* in_sizes, int n_in,
                              void* d_out, int out_size) {
    const float* x = (const float*)d_in[0];
    const int* kp = (const int*)d_in[1];
    long long n_x = (long long)in_sizes[0];
    long long out_n = (long long)out_size;
    // one CTA per row when k==64; grid-stride loop covers the general case
    int grid = (int)((out_n + 63) / 64);
    if (grid < 1) grid = 1;
    TopKPooling_20796231647786_kernel<<<grid, THREADS>>>(x, kp, (float*)d_out, n_x, out_n);
}

// round 2
// speedup vs baseline: 1.3357x; 1.3357x over previous
#include <cuda_runtime.h>
#include <cstdint>

#define THREADS 256
#define CAP 2048          // candidate buffer capacity (supports k <= CAP)

// Monotone float<->uint key mapping (total order matching IEEE float order)
__device__ __forceinline__ unsigned f2key(float f) {
    unsigned u = __float_as_uint(f);
    return (u & 0x80000000u) ? ~u : (u | 0x80000000u);
}
__device__ __forceinline__ float key2f(unsigned kk) {
    unsigned u = (kk & 0x80000000u) ? (kk ^ 0x80000000u) : ~kk;
    return __uint_as_float(u);
}

// Rare-path append of one float4's hits: one shared atomic for the pack.
__device__ __forceinline__ void append_pack(float4 v, float t0, float* s_cand, int* s_cnt) {
    int h = (v.x > t0) + (v.y > t0) + (v.z > t0) + (v.w > t0);
    int base = atomicAdd(s_cnt, h);
    int p = base;
    if (v.x > t0) { if (p < CAP) s_cand[p] = v.x; p++; }
    if (v.y > t0) { if (p < CAP) s_cand[p] = v.y; p++; }
    if (v.z > t0) { if (p < CAP) s_cand[p] = v.z; p++; }
    if (v.w > t0) { if (p < CAP) s_cand[p] = v.w; p++; }
}

// Exact ranking of M candidates; writes ranks < k. Tie-break by slot index:
// equal values are interchangeable, so the OUTPUT is deterministic regardless
// of the (atomic, unordered) insertion order.
__device__ __forceinline__ void rank_and_write(const float* s_cand, int M, int k,
                                               float* outr, int tid) {
    for (int i = tid; i < M; i += THREADS) {
        float vi = s_cand[i];
        int rank = 0;
        for (int j = 0; j < M; j++) {
            float vj = s_cand[j];
            rank += (vj > vi) || (vj == vi && j < i);
        }
        if (rank < k) outr[rank] = vi;
    }
}

__global__ void __launch_bounds__(THREADS)
TopKPooling_20796231647786_kernel(
    const float* __restrict__ x, const int* __restrict__ kp,
    float* __restrict__ out, long long n_x, long long out_n)
{
    __shared__ float s_cand[CAP];
    __shared__ int s_cnt;
    __shared__ int s_c2;

    const int k = *kp;
    const long long rows = out_n / k;
    const int row_len = (int)(n_x / rows);
    const int tid = threadIdx.x;
    const int lane = tid & 31;
    const float t0 = 2.35f;                  // fast-path pre-filter; fallback keeps it exact

    for (long long r = blockIdx.x; r < rows; r += gridDim.x) {
        const float* __restrict__ xr = x + r * (long long)row_len;
        float* __restrict__ outr = out + r * (long long)k;

        if (tid == 0) s_cnt = 0;
        __syncthreads();

        // ---- Fast path: single streaming pass. Common case per float4:
        // 3x FMNMX + FSETP + skip. Rare case: tiny atomic append block.
        const int nv4 = row_len >> 2;
        const float4* __restrict__ x4 = (const float4*)xr;

        int i = tid;
        // unrolled-by-4 main loop: 4 independent LDG.128 in flight per thread
        for (; i + 3 * THREADS < nv4; i += 4 * THREADS) {
            float4 a = __ldg(&x4[i]);
            float4 b = __ldg(&x4[i + THREADS]);
            float4 c = __ldg(&x4[i + 2 * THREADS]);
            float4 d = __ldg(&x4[i + 3 * THREADS]);
            float ma = fmaxf(fmaxf(a.x, a.y), fmaxf(a.z, a.w));
            float mb = fmaxf(fmaxf(b.x, b.y), fmaxf(b.z, b.w));
            float mc = fmaxf(fmaxf(c.x, c.y), fmaxf(c.z, c.w));
            float md = fmaxf(fmaxf(d.x, d.y), fmaxf(d.z, d.w));
            if (ma > t0) append_pack(a, t0, s_cand, &s_cnt);
            if (mb > t0) append_pack(b, t0, s_cand, &s_cnt);
            if (mc > t0) append_pack(c, t0, s_cand, &s_cnt);
            if (md > t0) append_pack(d, t0, s_cand, &s_cnt);
        }
        for (; i < nv4; i += THREADS) {
            float4 a = __ldg(&x4[i]);
            float ma = fmaxf(fmaxf(a.x, a.y), fmaxf(a.z, a.w));
            if (ma > t0) append_pack(a, t0, s_cand, &s_cnt);
        }
        // scalar tail for row_len not divisible by 4
        for (int j = (nv4 << 2) + tid; j < row_len; j += THREADS) {
            float f = __ldg(&xr[j]);
            if (f > t0) { int s = atomicAdd(&s_cnt, 1); if (s < CAP) s_cand[s] = f; }
        }
        __syncthreads();

        int c = s_cnt;
        if (c >= k && c <= CAP) {
            // all top-k are strictly > t0 and captured: exact rank among c candidates
            rank_and_write(s_cand, c, k, outr, tid);
        } else {
            // ---- Exact fallback: bisection for the k-th largest key (never taken on
            // the benchmark distribution; guarantees correctness for any input, k<=CAP)
            long long lo = -1, hi = 0xFFFFFFFFll;
            while (lo + 1 < hi) {
                long long mid = (lo + hi) >> 1;
                unsigned tkey = (unsigned)mid;
                if (tid == 0) s_c2 = 0;
                __syncthreads();
                int local = 0;
                for (int j = tid; j < row_len; j += THREADS)
                    local += (f2key(__ldg(&xr[j])) > tkey) ? 1 : 0;
                #pragma unroll
                for (int o = 16; o; o >>= 1) local += __shfl_down_sync(0xFFFFFFFFu, local, o);
                if (lane == 0) atomicAdd(&s_c2, local);
                __syncthreads();
                int cc = s_c2;
                if (cc < k) hi = mid; else lo = mid;
                __syncthreads();
            }
            unsigned K = (unsigned)hi;               // K = k-th largest key
            if (tid == 0) s_cnt = 0;
            __syncthreads();
            for (int j = tid; j < row_len; j += THREADS) {
                float f = __ldg(&xr[j]);
                if (f2key(f) > K) { int s = atomicAdd(&s_cnt, 1); if (s < CAP) s_cand[s] = f; }
            }
            __syncthreads();
            int M = s_cnt;                            // M < k <= CAP
            rank_and_write(s_cand, M, k, outr, tid);
            float fk = key2f(K);                      // fill duplicates of the k-th value
            for (int j = M + tid; j < k; j += THREADS) outr[j] = fk;
        }
        __syncthreads();   // protect s_cnt/s_cand reuse across row iterations
    }
}

extern "C" void kernel_launch(void* const* d_in, const int* in_sizes, int n_in,
                              void* d_out, int out_size) {
    const float* x = (const float*)d_in[0];
    const int* kp = (const int*)d_in[1];
    long long n_x = (long long)in_sizes[0];
    long long out_n = (long long)out_size;
    int grid = (int)((out_n + 63) / 64);   // one CTA per row when k==64
    if (grid < 1) grid = 1;
    TopKPooling_20796231647786_kernel<<<grid, THREADS>>>(x, kp, (float*)d_out, n_x, out_n);
}

// round 5
// speedup vs baseline: 1.4214x; 1.0642x over previous
#include <cuda_runtime.h>
#include <cstdint>

#define THREADS 256
#define CAP 2048          // candidate buffer capacity (supports k <= CAP)

// Monotone float<->uint key mapping (total order matching IEEE float order)
__device__ __forceinline__ unsigned f2key(float f) {
    unsigned u = __float_as_uint(f);
    return (u & 0x80000000u) ? ~u : (u | 0x80000000u);
}
__device__ __forceinline__ float key2f(unsigned kk) {
    unsigned u = (kk & 0x80000000u) ? (kk ^ 0x80000000u) : ~kk;
    return __uint_as_float(u);
}

// Rare-path append of one float4's hits (as integer keys): one shared atomic per pack.
__device__ __forceinline__ void append_pack(float4 v, float t0, unsigned* s_key, int* s_cnt) {
    int h = (v.x > t0) + (v.y > t0) + (v.z > t0) + (v.w > t0);
    int base = atomicAdd(s_cnt, h);
    int p = base;
    if (v.x > t0) { if (p < CAP) s_key[p] = f2key(v.x); p++; }
    if (v.y > t0) { if (p < CAP) s_key[p] = f2key(v.y); p++; }
    if (v.z > t0) { if (p < CAP) s_key[p] = f2key(v.z); p++; }
    if (v.w > t0) { if (p < CAP) s_key[p] = f2key(v.w); p++; }
}

// Exact ranking of M keys (zero-padded to Mpad, multiple of 4); writes ranks < k.
// rank_i = #{j<i : kj >= ki} + #{j>i : kj > ki}  == classic stable rank.
// Equal keys are interchangeable floats => output deterministic regardless of
// the (atomic, unordered) insertion order. Requires s_key 16B-aligned.
__device__ __forceinline__ void rank_and_write_keys(const unsigned* __restrict__ s_key,
                                                    int M, int k, float* __restrict__ outr,
                                                    int tid) {
    const int Mpad = (M + 3) & ~3;
    const uint4* __restrict__ k4 = (const uint4*)s_key;
    for (int i = tid; i < M; i += THREADS) {
        const unsigned ki = s_key[i];
        const int ib = i >> 2;          // block index containing i
        int rank = 0;
        // blocks fully before i's block: count kj >= ki
        #pragma unroll 4
        for (int b = 0; b < ib; b++) {
            uint4 v = k4[b];
            rank += (v.x >= ki) + (v.y >= ki) + (v.z >= ki) + (v.w >= ki);
        }
        // straddling block: elements before i use >=, at/after i use >
        {
            uint4 v = k4[ib];
            int m = i & 3;
            rank += (0 < m) ? (v.x >= ki) : (v.x > ki);
            rank += (1 < m) ? (v.y >= ki) : (v.y > ki);
            rank += (2 < m) ? (v.z >= ki) : (v.z > ki);
            rank += (3 < m) ? (v.w >= ki) : (v.w > ki);
        }
        // blocks fully after: count kj > ki  (pad keys are 0 -> contribute nothing)
        #pragma unroll 4
        for (int b = ib + 1; b < (Mpad >> 2); b++) {
            uint4 v = k4[b];
            rank += (v.x > ki) + (v.y > ki) + (v.z > ki) + (v.w > ki);
        }
        if (rank < k) outr[rank] = key2f(ki);
    }
}

__global__ void __launch_bounds__(THREADS)
TopKPooling_20796231647786_kernel(
    const float* __restrict__ x, const int* __restrict__ kp,
    float* __restrict__ out, long long n_x, long long out_n)
{
    __shared__ __align__(16) unsigned s_key[CAP];
    __shared__ int s_cnt;
    __shared__ int s_c2;

    const int k = *kp;
    const long long rows = out_n / k;
    const int row_len = (int)(n_x / rows);
    const int tid = threadIdx.x;
    const int lane = tid & 31;
    const float t0 = 2.35f;                  // fast-path pre-filter; fallback keeps it exact

    for (long long r = blockIdx.x; r < rows; r += gridDim.x) {
        const float* __restrict__ xr = x + r * (long long)row_len;
        float* __restrict__ outr = out + r * (long long)k;

        if (tid == 0) s_cnt = 0;
        __syncthreads();

        // ---- Fast path: single streaming pass. Common case per float4:
        // 3x FMNMX + FSETP + skip. Rare case: tiny atomic append block.
        const int nv4 = row_len >> 2;
        const float4* __restrict__ x4 = (const float4*)xr;

        int i = tid;
        for (; i + 3 * THREADS < nv4; i += 4 * THREADS) {
            float4 a = __ldg(&x4[i]);
            float4 b = __ldg(&x4[i + THREADS]);
            float4 c = __ldg(&x4[i + 2 * THREADS]);
            float4 d = __ldg(&x4[i + 3 * THREADS]);
            float ma = fmaxf(fmaxf(a.x, a.y), fmaxf(a.z, a.w));
            float mb = fmaxf(fmaxf(b.x, b.y), fmaxf(b.z, b.w));
            float mc = fmaxf(fmaxf(c.x, c.y), fmaxf(c.z, c.w));
            float md = fmaxf(fmaxf(d.x, d.y), fmaxf(d.z, d.w));
            if (ma > t0) append_pack(a, t0, s_key, &s_cnt);
            if (mb > t0) append_pack(b, t0, s_key, &s_cnt);
            if (mc > t0) append_pack(c, t0, s_key, &s_cnt);
            if (md > t0) append_pack(d, t0, s_key, &s_cnt);
        }
        for (; i < nv4; i += THREADS) {
            float4 a = __ldg(&x4[i]);
            float ma = fmaxf(fmaxf(a.x, a.y), fmaxf(a.z, a.w));
            if (ma > t0) append_pack(a, t0, s_key, &s_cnt);
        }
        for (int j = (nv4 << 2) + tid; j < row_len; j += THREADS) {
            float f = __ldg(&xr[j]);
            if (f > t0) { int s = atomicAdd(&s_cnt, 1); if (s < CAP) s_key[s] = f2key(f); }
        }
        __syncthreads();

        int c = s_cnt;
        if (c >= k && c <= CAP) {
            // zero-pad to multiple of 4 (pad key 0 < any candidate key)
            int Mpad = (c + 3) & ~3;
            if (tid < Mpad - c) s_key[c + tid] = 0;
            __syncthreads();
            rank_and_write_keys(s_key, c, k, outr, tid);
        } else {
            // ---- Exact fallback: bisection for the k-th largest key (never taken on
            // the benchmark distribution; guarantees correctness for any input, k<=CAP)
            long long lo = -1, hi = 0xFFFFFFFFll;
            while (lo + 1 < hi) {
                long long mid = (lo + hi) >> 1;
                unsigned tkey = (unsigned)mid;
                if (tid == 0) s_c2 = 0;
                __syncthreads();
                int local = 0;
                for (int j = tid; j < row_len; j += THREADS)
                    local += (f2key(__ldg(&xr[j])) > tkey) ? 1 : 0;
                #pragma unroll
                for (int o = 16; o; o >>= 1) local += __shfl_down_sync(0xFFFFFFFFu, local, o);
                if (lane == 0) atomicAdd(&s_c2, local);
                __syncthreads();
                int cc = s_c2;
                if (cc < k) hi = mid; else lo = mid;
                __syncthreads();
            }
            unsigned K = (unsigned)hi;               // K = k-th largest key
            if (tid == 0) s_cnt = 0;
            __syncthreads();
            for (int j = tid; j < row_len; j += THREADS) {
                unsigned kf = f2key(__ldg(&xr[j]));
                if (kf > K) { int s = atomicAdd(&s_cnt, 1); if (s < CAP) s_key[s] = kf; }
            }
            __syncthreads();
            int M = s_cnt;                            // M < k <= CAP
            int Mpad = (M + 3) & ~3;
            if (tid < Mpad - M) s_key[M + tid] = 0;
            __syncthreads();
            rank_and_write_keys(s_key, M, k, outr, tid);
            float fk = key2f(K);                      // fill duplicates of the k-th value
            for (int j = M + tid; j < k; j += THREADS) outr[j] = fk;
        }
        __syncthreads();   // protect s_cnt/s_key reuse across row iterations
    }
}

extern "C" void kernel_launch(void* const* d_in, const int* in_sizes, int n_in,
                              void* d_out, int out_size) {
    const float* x = (const float*)d_in[0];
    const int* kp = (const int*)d_in[1];
    long long n_x = (long long)in_sizes[0];
    long long out_n = (long long)out_size;
    int grid = (int)((out_n + 63) / 64);   // one CTA per row when k==64
    if (grid < 1) grid = 1;
    TopKPooling_20796231647786_kernel<<<grid, THREADS>>>(x, kp, (float*)d_out, n_x, out_n);
}